// round 3
// baseline (speedup 1.0000x reference)
#include <cuda_runtime.h>
#include <math.h>
#include <stdint.h>

#define N_NODES 100000
#define N_EDGES 3200000
#define D_IN    512
#define D_HID   256
#define D_OUT   64
#define KORD    10

// ---------------- device scratch (no allocations allowed) ----------------
__device__ int    g_cnt[N_NODES];
__device__ int    g_pos[N_NODES];
__device__ int    g_start[N_NODES + 1];
__device__ float  g_dinv[N_NODES];
__device__ int2   g_edge[N_EDGES];                       // (col, w bits) CSR by row
__device__ float  g_h1[(size_t)N_NODES * D_HID];          // MLP hidden
__device__ float  g_h [(size_t)N_NODES * D_OUT];          // MLP output (pre-prop)
__device__ float  g_r0[(size_t)N_NODES * D_OUT];
__device__ float  g_r1[(size_t)N_NODES * D_OUT];
__device__ float  g_coef[KORD + 1];                       // monomial coeffs of poly in A

// ---------------- CSR build ----------------
__global__ void zero_cnt_k() {
    int i = blockIdx.x * blockDim.x + threadIdx.x;
    if (i < N_NODES) g_cnt[i] = 0;
}

__global__ void hist_k(const int* __restrict__ row) {
    int e = blockIdx.x * blockDim.x + threadIdx.x;
    if (e < N_EDGES) atomicAdd(&g_cnt[row[e]], 1);
}

// single-block exclusive scan over g_cnt -> g_start/g_pos; also dinv = rsqrt(deg)
__global__ void scan_k() {
    __shared__ int wsum[32];
    __shared__ int s_carry;
    int tid = threadIdx.x, lane = tid & 31, warp = tid >> 5;
    if (tid == 0) s_carry = 0;
    __syncthreads();
    for (int base = 0; base < N_NODES; base += 1024) {
        int i = base + tid;
        int v = (i < N_NODES) ? g_cnt[i] : 0;
        int incl = v;
#pragma unroll
        for (int o = 1; o < 32; o <<= 1) {
            int t = __shfl_up_sync(0xFFFFFFFFu, incl, o);
            if (lane >= o) incl += t;
        }
        if (lane == 31) wsum[warp] = incl;
        __syncthreads();
        if (warp == 0) {
            int w = wsum[lane];
#pragma unroll
            for (int o = 1; o < 32; o <<= 1) {
                int t = __shfl_up_sync(0xFFFFFFFFu, w, o);
                if (lane >= o) w += t;
            }
            wsum[lane] = w;
        }
        __syncthreads();
        int woff  = (warp > 0) ? wsum[warp - 1] : 0;
        int carry = s_carry;
        if (i < N_NODES) {
            int excl = carry + woff + incl - v;
            g_start[i] = excl;
            g_pos[i]   = excl;
            g_dinv[i]  = (v > 0) ? rsqrtf((float)v) : 0.0f;
        }
        __syncthreads();
        if (tid == 1023) s_carry = carry + wsum[31];
        __syncthreads();
    }
    if (threadIdx.x == 0) g_start[N_NODES] = N_EDGES;
}

__global__ void scatter_k(const int* __restrict__ row, const int* __restrict__ col) {
    int e = blockIdx.x * blockDim.x + threadIdx.x;
    if (e < N_EDGES) {
        int r = row[e], c = col[e];
        int p = atomicAdd(&g_pos[r], 1);
        float w = g_dinv[r] * g_dinv[c];
        g_edge[p] = make_int2(c, __float_as_int(w));
    }
}

// ---------------- Bernstein -> monomial coefficients (exact in double) ----------------
__global__ void coef_k(const float* __restrict__ temp) {
    if (threadIdx.x != 0 || blockIdx.x != 0) return;
    double B[KORD + 1][KORD + 1];
    for (int n = 0; n <= KORD; n++) {
        for (int j = 0; j <= KORD; j++) B[n][j] = 0.0;
        B[n][0] = 1.0;
        for (int j = 1; j <= n; j++)
            B[n][j] = (j == n) ? 1.0 : (B[n - 1][j - 1] + B[n - 1][j]);
    }
    double a[KORD + 1];
    for (int j = 0; j <= KORD; j++) a[j] = 0.0;
    for (int k = 0; k <= KORD; k++) {
        double th = (double)temp[k];
        if (th < 0.0) th = 0.0;                       // relu
        double ck = th * B[KORD][k] / 1024.0;         // theta_k * C(K,k)/2^K
        for (int j = 0; j <= KORD; j++) {
            // coeff of x^j in (1-x)^k (1+x)^(K-k)
            double s = 0.0;
            for (int i = 0; i <= k; i++) {
                int l = j - i;
                if (l >= 0 && l <= KORD - k) {
                    double t = B[k][i] * B[KORD - k][l];
                    s += (i & 1) ? -t : t;
                }
            }
            a[j] += ck * s;
        }
    }
    for (int j = 0; j <= KORD; j++) g_coef[j] = (float)a[j];
}

// ---------------- SIMT fp32 GEMM with bias (+optional relu) ----------------
template <int BM, int BN, int BK, int TM, int TN, bool RELU>
__global__ void gemm_bias_k(const float* __restrict__ A, const float* __restrict__ B,
                            const float* __restrict__ bias, float* __restrict__ C,
                            int M, int Kd, int Nd) {
    __shared__ __align__(16) float As[BK][BM + 4];
    __shared__ __align__(16) float Bs[BK][BN];
    constexpr int THREADS = (BM / TM) * (BN / TN);   // 256
    const int tid  = threadIdx.x;
    const int m0   = blockIdx.y * BM;
    const int n0   = blockIdx.x * BN;
    const int trow = tid / (BN / TN);
    const int tcol = tid % (BN / TN);

    float acc[TM][TN];
#pragma unroll
    for (int i = 0; i < TM; i++)
#pragma unroll
        for (int j = 0; j < TN; j++) acc[i][j] = 0.0f;

    const int aRow = tid / (BK / 4);
    const int aCol = (tid % (BK / 4)) * 4;
    const int bRow = tid / (BN / 4);
    const int bCol = (tid % (BN / 4)) * 4;

    for (int kt = 0; kt < Kd; kt += BK) {
#pragma unroll
        for (int r = 0; r < BM; r += THREADS / (BK / 4)) {
            int gm = m0 + aRow + r;
            gm = min(gm, M - 1);
            float4 v = *reinterpret_cast<const float4*>(&A[(size_t)gm * Kd + kt + aCol]);
            As[aCol + 0][aRow + r] = v.x;
            As[aCol + 1][aRow + r] = v.y;
            As[aCol + 2][aRow + r] = v.z;
            As[aCol + 3][aRow + r] = v.w;
        }
#pragma unroll
        for (int r = 0; r < BK; r += THREADS / (BN / 4)) {
            float4 v = *reinterpret_cast<const float4*>(&B[(size_t)(kt + bRow + r) * Nd + n0 + bCol]);
            *reinterpret_cast<float4*>(&Bs[bRow + r][bCol]) = v;
        }
        __syncthreads();
#pragma unroll
        for (int k = 0; k < BK; k++) {
            float4 a0 = *reinterpret_cast<const float4*>(&As[k][trow * TM]);
            float4 a1 = *reinterpret_cast<const float4*>(&As[k][trow * TM + 4]);
            float4 b0 = *reinterpret_cast<const float4*>(&Bs[k][tcol * TN]);
            float ra[TM] = {a0.x, a0.y, a0.z, a0.w, a1.x, a1.y, a1.z, a1.w};
            float rb[TN] = {b0.x, b0.y, b0.z, b0.w};
#pragma unroll
            for (int i = 0; i < TM; i++)
#pragma unroll
                for (int j = 0; j < TN; j++) acc[i][j] += ra[i] * rb[j];
        }
        __syncthreads();
    }
    float4 bv = *reinterpret_cast<const float4*>(&bias[n0 + tcol * TN]);
#pragma unroll
    for (int i = 0; i < TM; i++) {
        int gm = m0 + trow * TM + i;
        if (gm < M) {
            float4 o;
            o.x = acc[i][0] + bv.x;
            o.y = acc[i][1] + bv.y;
            o.z = acc[i][2] + bv.z;
            o.w = acc[i][3] + bv.w;
            if (RELU) {
                o.x = fmaxf(o.x, 0.0f); o.y = fmaxf(o.y, 0.0f);
                o.z = fmaxf(o.z, 0.0f); o.w = fmaxf(o.w, 0.0f);
            }
            *reinterpret_cast<float4*>(&C[(size_t)gm * Nd + n0 + tcol * TN]) = o;
        }
    }
}

// ---------------- Horner step pieces ----------------
__global__ void scale_k(const float* __restrict__ h, float* __restrict__ r) {
    int i = blockIdx.x * blockDim.x + threadIdx.x;          // over N*64/4 float4s
    if (i < (N_NODES * D_OUT) / 4) {
        float a = g_coef[KORD];
        float4 v = reinterpret_cast<const float4*>(h)[i];
        v.x *= a; v.y *= a; v.z *= a; v.w *= a;
        reinterpret_cast<float4*>(r)[i] = v;
    }
}

// r_out = A_hat * r_in + a_j * h   (warp per row, float2 per lane = 64 feats)
__global__ void spmv_k(const float* __restrict__ vin, float* __restrict__ vout,
                       const float* __restrict__ h, int jcoef) {
    int wid  = (blockIdx.x * blockDim.x + threadIdx.x) >> 5;
    int lane = threadIdx.x & 31;
    if (wid >= N_NODES) return;
    float aj = g_coef[jcoef];
    float2 hv = reinterpret_cast<const float2*>(h)[(size_t)wid * 32 + lane];
    float accx = aj * hv.x;
    float accy = aj * hv.y;
    int s = g_start[wid];
    int e = g_start[wid + 1];
    for (int idx = s; idx < e; ++idx) {
        int2 ed = g_edge[idx];
        float w = __int_as_float(ed.y);
        float2 vv = reinterpret_cast<const float2*>(vin)[(size_t)ed.x * 32 + lane];
        accx = fmaf(w, vv.x, accx);
        accy = fmaf(w, vv.y, accy);
    }
    reinterpret_cast<float2*>(vout)[(size_t)wid * 32 + lane] = make_float2(accx, accy);
}

// ---------------- log_softmax over 64 classes, warp per row ----------------
__global__ void lsm_k(const float* __restrict__ in, float* __restrict__ out) {
    int wid  = (blockIdx.x * blockDim.x + threadIdx.x) >> 5;
    int lane = threadIdx.x & 31;
    if (wid >= N_NODES) return;
    float2 v = reinterpret_cast<const float2*>(in)[(size_t)wid * 32 + lane];
    float m = fmaxf(v.x, v.y);
#pragma unroll
    for (int o = 16; o; o >>= 1) m = fmaxf(m, __shfl_xor_sync(0xFFFFFFFFu, m, o));
    float s = expf(v.x - m) + expf(v.y - m);
#pragma unroll
    for (int o = 16; o; o >>= 1) s += __shfl_xor_sync(0xFFFFFFFFu, s, o);
    float l = m + logf(s);
    reinterpret_cast<float2*>(out)[(size_t)wid * 32 + lane] = make_float2(v.x - l, v.y - l);
}

// ---------------- launcher ----------------
extern "C" void kernel_launch(void* const* d_in, const int* in_sizes, int n_in,
                              void* d_out, int out_size) {
    const float* x    = (const float*)d_in[0];
    const int*   ei   = (const int*)  d_in[1];
    const float* W1   = (const float*)d_in[2];
    const float* b1   = (const float*)d_in[3];
    const float* W2   = (const float*)d_in[4];
    const float* b2   = (const float*)d_in[5];
    const float* temp = (const float*)d_in[6];
    float*       out  = (float*)d_out;
    const int* row = ei;
    const int* col = ei + N_EDGES;

    float *ph1, *ph, *pr0, *pr1;
    cudaGetSymbolAddress((void**)&ph1, g_h1);
    cudaGetSymbolAddress((void**)&ph,  g_h);
    cudaGetSymbolAddress((void**)&pr0, g_r0);
    cudaGetSymbolAddress((void**)&pr1, g_r1);

    // CSR build + coefficients
    zero_cnt_k<<<(N_NODES + 255) / 256, 256>>>();
    hist_k<<<(N_EDGES + 255) / 256, 256>>>(row);
    scan_k<<<1, 1024>>>();
    scatter_k<<<(N_EDGES + 255) / 256, 256>>>(row, col);
    coef_k<<<1, 32>>>(temp);

    // MLP
    dim3 g1(D_HID / 64, (N_NODES + 127) / 128);
    gemm_bias_k<128, 64, 16, 8, 4, true><<<g1, 256>>>(x, W1, b1, ph1, N_NODES, D_IN, D_HID);
    dim3 g2(D_OUT / 64, (N_NODES + 127) / 128);
    gemm_bias_k<128, 64, 16, 8, 4, false><<<g2, 256>>>(ph1, W2, b2, ph, N_NODES, D_HID, D_OUT);

    // Horner evaluation of the degree-K polynomial in A_hat
    const int warp_blocks = (N_NODES * 32 + 255) / 256;
    scale_k<<<((N_NODES * D_OUT) / 4 + 255) / 256, 256>>>(ph, pr0);
    float* rcur = pr0;
    float* rnxt = pr1;
    for (int j = KORD - 1; j >= 0; j--) {
        spmv_k<<<warp_blocks, 256>>>(rcur, rnxt, ph, j);
        float* t = rcur; rcur = rnxt; rnxt = t;
    }

    lsm_k<<<warp_blocks, 256>>>(rcur, out);
}

// round 5
// speedup vs baseline: 1.3026x; 1.3026x over previous
#include <cuda_runtime.h>
#include <math.h>
#include <stdint.h>

#define N_NODES 100000
#define N_EDGES 3200000
#define D_IN    512
#define D_HID   256
#define D_OUT   64
#define KORD    10

// ---------------- device scratch (no allocations allowed) ----------------
__device__ int    g_cnt[N_NODES];
__device__ int    g_pos[N_NODES];
__device__ int    g_start[N_NODES + 1];
__device__ float  g_dinv[N_NODES];
__device__ int2   g_edge[N_EDGES];                        // (col, w bits) CSR by row
__device__ float  g_h1[(size_t)N_NODES * D_HID];          // MLP hidden
__device__ float  g_h [(size_t)N_NODES * D_OUT];          // MLP output (pre-prop)
__device__ float  g_r0[(size_t)N_NODES * D_OUT];
__device__ float  g_r1[(size_t)N_NODES * D_OUT];
__device__ float  g_coef[KORD + 1];                       // monomial coeffs of poly in A

// ---------------- CSR build ----------------
__global__ void zero_cnt_k() {
    int i = blockIdx.x * blockDim.x + threadIdx.x;
    if (i < N_NODES) g_cnt[i] = 0;
}

__global__ void hist_k(const int* __restrict__ row) {
    int e = blockIdx.x * blockDim.x + threadIdx.x;
    if (e < N_EDGES) atomicAdd(&g_cnt[row[e]], 1);
}

// single-block exclusive scan over g_cnt -> g_start/g_pos; also dinv = rsqrt(deg)
__global__ void scan_k() {
    __shared__ int wsum[32];
    __shared__ int s_carry;
    int tid = threadIdx.x, lane = tid & 31, warp = tid >> 5;
    if (tid == 0) s_carry = 0;
    __syncthreads();
    for (int base = 0; base < N_NODES; base += 1024) {
        int i = base + tid;
        int v = (i < N_NODES) ? g_cnt[i] : 0;
        int incl = v;
#pragma unroll
        for (int o = 1; o < 32; o <<= 1) {
            int t = __shfl_up_sync(0xFFFFFFFFu, incl, o);
            if (lane >= o) incl += t;
        }
        if (lane == 31) wsum[warp] = incl;
        __syncthreads();
        if (warp == 0) {
            int w = wsum[lane];
#pragma unroll
            for (int o = 1; o < 32; o <<= 1) {
                int t = __shfl_up_sync(0xFFFFFFFFu, w, o);
                if (lane >= o) w += t;
            }
            wsum[lane] = w;
        }
        __syncthreads();
        int woff  = (warp > 0) ? wsum[warp - 1] : 0;
        int carry = s_carry;
        if (i < N_NODES) {
            int excl = carry + woff + incl - v;
            g_start[i] = excl;
            g_pos[i]   = excl;
            g_dinv[i]  = (v > 0) ? rsqrtf((float)v) : 0.0f;
        }
        __syncthreads();
        if (tid == 1023) s_carry = carry + wsum[31];
        __syncthreads();
    }
    if (threadIdx.x == 0) g_start[N_NODES] = N_EDGES;
}

__global__ void scatter_k(const int* __restrict__ row, const int* __restrict__ col) {
    int e = blockIdx.x * blockDim.x + threadIdx.x;
    if (e < N_EDGES) {
        int r = row[e], c = col[e];
        int p = atomicAdd(&g_pos[r], 1);
        float w = g_dinv[r] * g_dinv[c];
        g_edge[p] = make_int2(c, __float_as_int(w));
    }
}

// ---------------- Bernstein -> monomial coefficients (exact in double) ----------------
__global__ void coef_k(const float* __restrict__ temp) {
    if (threadIdx.x != 0 || blockIdx.x != 0) return;
    double B[KORD + 1][KORD + 1];
    for (int n = 0; n <= KORD; n++) {
        for (int j = 0; j <= KORD; j++) B[n][j] = 0.0;
        B[n][0] = 1.0;
        for (int j = 1; j <= n; j++)
            B[n][j] = (j == n) ? 1.0 : (B[n - 1][j - 1] + B[n - 1][j]);
    }
    double a[KORD + 1];
    for (int j = 0; j <= KORD; j++) a[j] = 0.0;
    for (int k = 0; k <= KORD; k++) {
        double th = (double)temp[k];
        if (th < 0.0) th = 0.0;                       // relu
        double ck = th * B[KORD][k] / 1024.0;         // theta_k * C(K,k)/2^K
        for (int j = 0; j <= KORD; j++) {
            double s = 0.0;
            for (int i = 0; i <= k; i++) {
                int l = j - i;
                if (l >= 0 && l <= KORD - k) {
                    double t = B[k][i] * B[KORD - k][l];
                    s += (i & 1) ? -t : t;
                }
            }
            a[j] += ck * s;
        }
    }
    for (int j = 0; j <= KORD; j++) g_coef[j] = (float)a[j];
}

// ---------------- tf32 tensor-core GEMM (mma.sync m16n8k8) ----------------
__device__ __forceinline__ uint32_t f2tf(float f) {
    uint32_t u;
    asm("cvt.rna.tf32.f32 %0, %1;" : "=r"(u) : "f"(f));
    return u;
}

__device__ __forceinline__ void mma_tf32(float* d, const uint32_t* a, const uint32_t* b) {
    asm volatile(
        "mma.sync.aligned.m16n8k8.row.col.f32.tf32.tf32.f32 "
        "{%0,%1,%2,%3}, {%4,%5,%6,%7}, {%8,%9}, {%0,%1,%2,%3};"
        : "+f"(d[0]), "+f"(d[1]), "+f"(d[2]), "+f"(d[3])
        : "r"(a[0]), "r"(a[1]), "r"(a[2]), "r"(a[3]), "r"(b[0]), "r"(b[1]));
}

// BM x BN block tile, BK=16, 256 threads as WMxWN warps; warp tile (BM/WM)x(BN/WN).
// A: [M,Kd] row-major fp32; B: [Kd,Nd] row-major fp32; C = relu?(A@B + bias).
template <int BM, int BN, int WM, int WN, bool RELU>
__launch_bounds__(256)
__global__ void gemm_tc_k(const float* __restrict__ A, const float* __restrict__ B,
                          const float* __restrict__ bias, float* __restrict__ C,
                          int M, int Kd, int Nd) {
    constexpr int BK = 16;
    constexpr int APITCH = BK + 4;        // 20 words  (80B rows, 16B aligned)
    constexpr int BPITCH = BN + 8;        // 136/72 words, 16B aligned rows
    constexpr int WTM = BM / WM;          // warp tile M
    constexpr int WTN = BN / WN;          // warp tile N
    constexpr int MT = WTM / 16;          // m16 tiles per warp
    constexpr int NT = WTN / 8;           // n8 tiles per warp
    constexpr int AV = (BM * BK) / (256 * 4);   // float4 loads per thread (A)
    constexpr int BV = (BK * BN) / (256 * 4);   // float4 loads per thread (B)

    __shared__ __align__(16) uint32_t As[BM * APITCH];
    __shared__ __align__(16) uint32_t Bs[BK * BPITCH];

    const int tid  = threadIdx.x;
    const int lane = tid & 31;
    const int w    = tid >> 5;
    const int wm   = w % WM;
    const int wn   = w / WM;
    const int m0   = blockIdx.y * BM;
    const int n0   = blockIdx.x * BN;

    float acc[MT][NT][4];
#pragma unroll
    for (int i = 0; i < MT; i++)
#pragma unroll
        for (int j = 0; j < NT; j++)
#pragma unroll
            for (int q = 0; q < 4; q++) acc[i][j][q] = 0.0f;

    float4 aS[AV], bS[BV];

    // prefetch tile 0
#pragma unroll
    for (int i = 0; i < AV; i++) {
        int idx = tid + i * 256;
        int r = idx >> 2, cv = (idx & 3) * 4;
        int gm = min(m0 + r, M - 1);
        aS[i] = *reinterpret_cast<const float4*>(&A[(size_t)gm * Kd + cv]);
    }
#pragma unroll
    for (int i = 0; i < BV; i++) {
        int idx = tid + i * 256;
        int r = idx / (BN / 4), c = (idx % (BN / 4)) * 4;
        bS[i] = *reinterpret_cast<const float4*>(&B[(size_t)r * Nd + n0 + c]);
    }

    for (int kt = 0; kt < Kd; kt += BK) {
        // stage regs -> smem (convert to tf32)
#pragma unroll
        for (int i = 0; i < AV; i++) {
            int idx = tid + i * 256;
            int r = idx >> 2, cv = (idx & 3) * 4;
            uint4 u = make_uint4(f2tf(aS[i].x), f2tf(aS[i].y), f2tf(aS[i].z), f2tf(aS[i].w));
            *reinterpret_cast<uint4*>(&As[r * APITCH + cv]) = u;
        }
#pragma unroll
        for (int i = 0; i < BV; i++) {
            int idx = tid + i * 256;
            int r = idx / (BN / 4), c = (idx % (BN / 4)) * 4;
            uint4 u = make_uint4(f2tf(bS[i].x), f2tf(bS[i].y), f2tf(bS[i].z), f2tf(bS[i].w));
            *reinterpret_cast<uint4*>(&Bs[r * BPITCH + c]) = u;
        }
        __syncthreads();

        // prefetch next tile
        if (kt + BK < Kd) {
#pragma unroll
            for (int i = 0; i < AV; i++) {
                int idx = tid + i * 256;
                int r = idx >> 2, cv = (idx & 3) * 4;
                int gm = min(m0 + r, M - 1);
                aS[i] = *reinterpret_cast<const float4*>(&A[(size_t)gm * Kd + kt + BK + cv]);
            }
#pragma unroll
            for (int i = 0; i < BV; i++) {
                int idx = tid + i * 256;
                int r = idx / (BN / 4), c = (idx % (BN / 4)) * 4;
                bS[i] = *reinterpret_cast<const float4*>(&B[(size_t)(kt + BK + r) * Nd + n0 + c]);
            }
        }

        // compute 2 k8 chunks
#pragma unroll
        for (int ch = 0; ch < 2; ch++) {
            uint32_t afr[MT][4], bfr[NT][2];
#pragma unroll
            for (int mt = 0; mt < MT; mt++) {
                int r = wm * WTM + mt * 16 + (lane >> 2);
                int c = ch * 8 + (lane & 3);
                afr[mt][0] = As[r * APITCH + c];
                afr[mt][1] = As[(r + 8) * APITCH + c];
                afr[mt][2] = As[r * APITCH + c + 4];
                afr[mt][3] = As[(r + 8) * APITCH + c + 4];
            }
#pragma unroll
            for (int nt = 0; nt < NT; nt++) {
                int kk = ch * 8 + (lane & 3);
                int n  = wn * WTN + nt * 8 + (lane >> 2);
                bfr[nt][0] = Bs[kk * BPITCH + n];
                bfr[nt][1] = Bs[(kk + 4) * BPITCH + n];
            }
#pragma unroll
            for (int mt = 0; mt < MT; mt++)
#pragma unroll
                for (int nt = 0; nt < NT; nt++)
                    mma_tf32(acc[mt][nt], afr[mt], bfr[nt]);
        }
        __syncthreads();
    }

    // epilogue: bias (+relu), float2 stores
#pragma unroll
    for (int mt = 0; mt < MT; mt++) {
#pragma unroll
        for (int nt = 0; nt < NT; nt++) {
            int col = n0 + wn * WTN + nt * 8 + (lane & 3) * 2;
            float bx = bias[col], by = bias[col + 1];
            int r0 = m0 + wm * WTM + mt * 16 + (lane >> 2);
            float vx = acc[mt][nt][0] + bx;
            float vy = acc[mt][nt][1] + by;
            if (RELU) { vx = fmaxf(vx, 0.0f); vy = fmaxf(vy, 0.0f); }
            if (r0 < M)
                *reinterpret_cast<float2*>(&C[(size_t)r0 * Nd + col]) = make_float2(vx, vy);
            int r1 = r0 + 8;
            vx = acc[mt][nt][2] + bx;
            vy = acc[mt][nt][3] + by;
            if (RELU) { vx = fmaxf(vx, 0.0f); vy = fmaxf(vy, 0.0f); }
            if (r1 < M)
                *reinterpret_cast<float2*>(&C[(size_t)r1 * Nd + col]) = make_float2(vx, vy);
        }
    }
}

// ---------------- Horner step pieces ----------------
__global__ void scale_k(const float* __restrict__ h, float* __restrict__ r) {
    int i = blockIdx.x * blockDim.x + threadIdx.x;
    if (i < (N_NODES * D_OUT) / 4) {
        float a = g_coef[KORD];
        float4 v = reinterpret_cast<const float4*>(h)[i];
        v.x *= a; v.y *= a; v.z *= a; v.w *= a;
        reinterpret_cast<float4*>(r)[i] = v;
    }
}

// r_out = A_hat * r_in + a_j * h   (warp per row, float2 per lane = 64 feats)
// manual 4-edge batches for MLP=4 against L2 latency
__global__ void spmv_k(const float* __restrict__ vin, float* __restrict__ vout,
                       const float* __restrict__ h, int jcoef) {
    int wid  = (blockIdx.x * blockDim.x + threadIdx.x) >> 5;
    int lane = threadIdx.x & 31;
    if (wid >= N_NODES) return;
    float aj = g_coef[jcoef];
    float2 hv = reinterpret_cast<const float2*>(h)[(size_t)wid * 32 + lane];
    float accx = aj * hv.x;
    float accy = aj * hv.y;
    int idx = g_start[wid];
    int e   = g_start[wid + 1];
    const float2* vin2 = reinterpret_cast<const float2*>(vin);
    for (; idx + 4 <= e; idx += 4) {
        int2 e0 = g_edge[idx + 0];
        int2 e1 = g_edge[idx + 1];
        int2 e2 = g_edge[idx + 2];
        int2 e3 = g_edge[idx + 3];
        float2 v0 = vin2[(size_t)e0.x * 32 + lane];
        float2 v1 = vin2[(size_t)e1.x * 32 + lane];
        float2 v2 = vin2[(size_t)e2.x * 32 + lane];
        float2 v3 = vin2[(size_t)e3.x * 32 + lane];
        float w0 = __int_as_float(e0.y), w1 = __int_as_float(e1.y);
        float w2 = __int_as_float(e2.y), w3 = __int_as_float(e3.y);
        accx = fmaf(w0, v0.x, accx); accy = fmaf(w0, v0.y, accy);
        accx = fmaf(w1, v1.x, accx); accy = fmaf(w1, v1.y, accy);
        accx = fmaf(w2, v2.x, accx); accy = fmaf(w2, v2.y, accy);
        accx = fmaf(w3, v3.x, accx); accy = fmaf(w3, v3.y, accy);
    }
    for (; idx < e; ++idx) {
        int2 ed = g_edge[idx];
        float w = __int_as_float(ed.y);
        float2 vv = vin2[(size_t)ed.x * 32 + lane];
        accx = fmaf(w, vv.x, accx);
        accy = fmaf(w, vv.y, accy);
    }
    reinterpret_cast<float2*>(vout)[(size_t)wid * 32 + lane] = make_float2(accx, accy);
}

// ---------------- log_softmax over 64 classes, warp per row ----------------
__global__ void lsm_k(const float* __restrict__ in, float* __restrict__ out) {
    int wid  = (blockIdx.x * blockDim.x + threadIdx.x) >> 5;
    int lane = threadIdx.x & 31;
    if (wid >= N_NODES) return;
    float2 v = reinterpret_cast<const float2*>(in)[(size_t)wid * 32 + lane];
    float m = fmaxf(v.x, v.y);
#pragma unroll
    for (int o = 16; o; o >>= 1) m = fmaxf(m, __shfl_xor_sync(0xFFFFFFFFu, m, o));
    float s = expf(v.x - m) + expf(v.y - m);
#pragma unroll
    for (int o = 16; o; o >>= 1) s += __shfl_xor_sync(0xFFFFFFFFu, s, o);
    float l = m + logf(s);
    reinterpret_cast<float2*>(out)[(size_t)wid * 32 + lane] = make_float2(v.x - l, v.y - l);
}

// ---------------- launcher ----------------
extern "C" void kernel_launch(void* const* d_in, const int* in_sizes, int n_in,
                              void* d_out, int out_size) {
    const float* x    = (const float*)d_in[0];
    const int*   ei   = (const int*)  d_in[1];
    const float* W1   = (const float*)d_in[2];
    const float* b1   = (const float*)d_in[3];
    const float* W2   = (const float*)d_in[4];
    const float* b2   = (const float*)d_in[5];
    const float* temp = (const float*)d_in[6];
    float*       out  = (float*)d_out;
    const int* row = ei;
    const int* col = ei + N_EDGES;

    float *ph1, *ph, *pr0, *pr1;
    cudaGetSymbolAddress((void**)&ph1, g_h1);
    cudaGetSymbolAddress((void**)&ph,  g_h);
    cudaGetSymbolAddress((void**)&pr0, g_r0);
    cudaGetSymbolAddress((void**)&pr1, g_r1);

    // CSR build + coefficients
    zero_cnt_k<<<(N_NODES + 255) / 256, 256>>>();
    hist_k<<<(N_EDGES + 255) / 256, 256>>>(row);
    scan_k<<<1, 1024>>>();
    scatter_k<<<(N_EDGES + 255) / 256, 256>>>(row, col);
    coef_k<<<1, 32>>>(temp);

    // MLP on tensor cores (tf32 mma)
    {
        dim3 g1(D_HID / 128, (N_NODES + 127) / 128);
        gemm_tc_k<128, 128, 2, 4, true><<<g1, 256>>>(x, W1, b1, ph1, N_NODES, D_IN, D_HID);
        dim3 g2(D_OUT / 64, (N_NODES + 127) / 128);
        gemm_tc_k<128, 64, 4, 2, false><<<g2, 256>>>(ph1, W2, b2, ph, N_NODES, D_HID, D_OUT);
    }

    // Horner evaluation of the degree-K polynomial in A_hat
    const int warp_blocks = (N_NODES * 32 + 255) / 256;
    scale_k<<<((N_NODES * D_OUT) / 4 + 255) / 256, 256>>>(ph, pr0);
    float* rcur = pr0;
    float* rnxt = pr1;
    for (int j = KORD - 1; j >= 0; j--) {
        spmv_k<<<warp_blocks, 256>>>(rcur, rnxt, ph, j);
        float* t = rcur; rcur = rnxt; rnxt = t;
    }

    lsm_k<<<warp_blocks, 256>>>(rcur, out);
}

// round 6
// speedup vs baseline: 1.4982x; 1.1502x over previous
#include <cuda_runtime.h>
#include <cuda_fp16.h>
#include <math.h>
#include <stdint.h>

#define N_NODES 100000
#define N_EDGES 3200000
#define D_IN    512
#define D_HID   256
#define D_OUT   64
#define KORD    10

// ---------------- device scratch (no allocations allowed) ----------------
__device__ int     g_cnt[N_NODES];
__device__ int     g_pos[N_NODES];
__device__ int     g_start[N_NODES + 1];
__device__ float   g_dinv[N_NODES];
__device__ int2    g_edge[N_EDGES];                        // (col, w bits) CSR by row
__device__ float   g_h1[(size_t)N_NODES * D_HID];          // MLP hidden
__device__ float   g_h [(size_t)N_NODES * D_OUT];          // MLP output fp32
__device__ __half2 g_hh[(size_t)N_NODES * (D_OUT / 2)];    // MLP output fp16 (for gathers)
__device__ __half2 g_q0[(size_t)N_NODES * (D_OUT / 2)];    // Horner intermediates (fp16)
__device__ __half2 g_q1[(size_t)N_NODES * (D_OUT / 2)];
__device__ float   g_coef[KORD + 1];                       // monomial coeffs of poly in A

// ---------------- CSR build ----------------
__global__ void zero_cnt_k() {
    int i = blockIdx.x * blockDim.x + threadIdx.x;
    if (i < N_NODES) g_cnt[i] = 0;
}

__global__ void hist_k(const int* __restrict__ row) {
    int e = blockIdx.x * blockDim.x + threadIdx.x;
    if (e < N_EDGES) atomicAdd(&g_cnt[row[e]], 1);
}

// single-block exclusive scan over g_cnt -> g_start/g_pos; also dinv = rsqrt(deg)
__global__ void scan_k() {
    __shared__ int wsum[32];
    __shared__ int s_carry;
    int tid = threadIdx.x, lane = tid & 31, warp = tid >> 5;
    if (tid == 0) s_carry = 0;
    __syncthreads();
    for (int base = 0; base < N_NODES; base += 1024) {
        int i = base + tid;
        int v = (i < N_NODES) ? g_cnt[i] : 0;
        int incl = v;
#pragma unroll
        for (int o = 1; o < 32; o <<= 1) {
            int t = __shfl_up_sync(0xFFFFFFFFu, incl, o);
            if (lane >= o) incl += t;
        }
        if (lane == 31) wsum[warp] = incl;
        __syncthreads();
        if (warp == 0) {
            int w = wsum[lane];
#pragma unroll
            for (int o = 1; o < 32; o <<= 1) {
                int t = __shfl_up_sync(0xFFFFFFFFu, w, o);
                if (lane >= o) w += t;
            }
            wsum[lane] = w;
        }
        __syncthreads();
        int woff  = (warp > 0) ? wsum[warp - 1] : 0;
        int carry = s_carry;
        if (i < N_NODES) {
            int excl = carry + woff + incl - v;
            g_start[i] = excl;
            g_pos[i]   = excl;
            g_dinv[i]  = (v > 0) ? rsqrtf((float)v) : 0.0f;
        }
        __syncthreads();
        if (tid == 1023) s_carry = carry + wsum[31];
        __syncthreads();
    }
    if (threadIdx.x == 0) g_start[N_NODES] = N_EDGES;
}

__global__ void scatter_k(const int* __restrict__ row, const int* __restrict__ col) {
    int e = blockIdx.x * blockDim.x + threadIdx.x;
    if (e < N_EDGES) {
        int r = row[e], c = col[e];
        int p = atomicAdd(&g_pos[r], 1);
        float w = g_dinv[r] * g_dinv[c];
        g_edge[p] = make_int2(c, __float_as_int(w));
    }
}

// ---------------- Bernstein -> monomial coefficients (exact in double) ----------------
__global__ void coef_k(const float* __restrict__ temp) {
    if (threadIdx.x != 0 || blockIdx.x != 0) return;
    double B[KORD + 1][KORD + 1];
    for (int n = 0; n <= KORD; n++) {
        for (int j = 0; j <= KORD; j++) B[n][j] = 0.0;
        B[n][0] = 1.0;
        for (int j = 1; j <= n; j++)
            B[n][j] = (j == n) ? 1.0 : (B[n - 1][j - 1] + B[n - 1][j]);
    }
    double a[KORD + 1];
    for (int j = 0; j <= KORD; j++) a[j] = 0.0;
    for (int k = 0; k <= KORD; k++) {
        double th = (double)temp[k];
        if (th < 0.0) th = 0.0;                       // relu
        double ck = th * B[KORD][k] / 1024.0;         // theta_k * C(K,k)/2^K
        for (int j = 0; j <= KORD; j++) {
            double s = 0.0;
            for (int i = 0; i <= k; i++) {
                int l = j - i;
                if (l >= 0 && l <= KORD - k) {
                    double t = B[k][i] * B[KORD - k][l];
                    s += (i & 1) ? -t : t;
                }
            }
            a[j] += ck * s;
        }
    }
    for (int j = 0; j <= KORD; j++) g_coef[j] = (float)a[j];
}

// ---------------- tf32 tensor-core GEMM (mma.sync m16n8k8) ----------------
__device__ __forceinline__ uint32_t f2tf(float f) {
    uint32_t u;
    asm("cvt.rna.tf32.f32 %0, %1;" : "=r"(u) : "f"(f));
    return u;
}

__device__ __forceinline__ void mma_tf32(float* d, const uint32_t* a, const uint32_t* b) {
    asm volatile(
        "mma.sync.aligned.m16n8k8.row.col.f32.tf32.tf32.f32 "
        "{%0,%1,%2,%3}, {%4,%5,%6,%7}, {%8,%9}, {%0,%1,%2,%3};"
        : "+f"(d[0]), "+f"(d[1]), "+f"(d[2]), "+f"(d[3])
        : "r"(a[0]), "r"(a[1]), "r"(a[2]), "r"(a[3]), "r"(b[0]), "r"(b[1]));
}

// BM x BN block tile, BK=16, 256 threads as WMxWN warps; warp tile (BM/WM)x(BN/WN).
// A: [M,Kd] row-major fp32; B: [Kd,Nd] row-major fp32; C = relu?(A@B + bias).
// If WH, additionally writes a fp16 copy of C to Ch.
template <int BM, int BN, int WM, int WN, bool RELU, bool WH>
__launch_bounds__(256)
__global__ void gemm_tc_k(const float* __restrict__ A, const float* __restrict__ B,
                          const float* __restrict__ bias, float* __restrict__ C,
                          __half2* __restrict__ Ch, int M, int Kd, int Nd) {
    constexpr int BK = 16;
    constexpr int APITCH = BK + 4;
    constexpr int BPITCH = BN + 8;
    constexpr int WTM = BM / WM;
    constexpr int WTN = BN / WN;
    constexpr int MT = WTM / 16;
    constexpr int NT = WTN / 8;
    constexpr int AV = (BM * BK) / (256 * 4);
    constexpr int BV = (BK * BN) / (256 * 4);

    __shared__ __align__(16) uint32_t As[BM * APITCH];
    __shared__ __align__(16) uint32_t Bs[BK * BPITCH];

    const int tid  = threadIdx.x;
    const int lane = tid & 31;
    const int w    = tid >> 5;
    const int wm   = w % WM;
    const int wn   = w / WM;
    const int m0   = blockIdx.y * BM;
    const int n0   = blockIdx.x * BN;

    float acc[MT][NT][4];
#pragma unroll
    for (int i = 0; i < MT; i++)
#pragma unroll
        for (int j = 0; j < NT; j++)
#pragma unroll
            for (int q = 0; q < 4; q++) acc[i][j][q] = 0.0f;

    float4 aS[AV], bS[BV];

#pragma unroll
    for (int i = 0; i < AV; i++) {
        int idx = tid + i * 256;
        int r = idx >> 2, cv = (idx & 3) * 4;
        int gm = min(m0 + r, M - 1);
        aS[i] = *reinterpret_cast<const float4*>(&A[(size_t)gm * Kd + cv]);
    }
#pragma unroll
    for (int i = 0; i < BV; i++) {
        int idx = tid + i * 256;
        int r = idx / (BN / 4), c = (idx % (BN / 4)) * 4;
        bS[i] = *reinterpret_cast<const float4*>(&B[(size_t)r * Nd + n0 + c]);
    }

    for (int kt = 0; kt < Kd; kt += BK) {
#pragma unroll
        for (int i = 0; i < AV; i++) {
            int idx = tid + i * 256;
            int r = idx >> 2, cv = (idx & 3) * 4;
            uint4 u = make_uint4(f2tf(aS[i].x), f2tf(aS[i].y), f2tf(aS[i].z), f2tf(aS[i].w));
            *reinterpret_cast<uint4*>(&As[r * APITCH + cv]) = u;
        }
#pragma unroll
        for (int i = 0; i < BV; i++) {
            int idx = tid + i * 256;
            int r = idx / (BN / 4), c = (idx % (BN / 4)) * 4;
            uint4 u = make_uint4(f2tf(bS[i].x), f2tf(bS[i].y), f2tf(bS[i].z), f2tf(bS[i].w));
            *reinterpret_cast<uint4*>(&Bs[r * BPITCH + c]) = u;
        }
        __syncthreads();

        if (kt + BK < Kd) {
#pragma unroll
            for (int i = 0; i < AV; i++) {
                int idx = tid + i * 256;
                int r = idx >> 2, cv = (idx & 3) * 4;
                int gm = min(m0 + r, M - 1);
                aS[i] = *reinterpret_cast<const float4*>(&A[(size_t)gm * Kd + kt + BK + cv]);
            }
#pragma unroll
            for (int i = 0; i < BV; i++) {
                int idx = tid + i * 256;
                int r = idx / (BN / 4), c = (idx % (BN / 4)) * 4;
                bS[i] = *reinterpret_cast<const float4*>(&B[(size_t)(kt + BK + r) * Nd + n0 + c]);
            }
        }

#pragma unroll
        for (int ch = 0; ch < 2; ch++) {
            uint32_t afr[MT][4], bfr[NT][2];
#pragma unroll
            for (int mt = 0; mt < MT; mt++) {
                int r = wm * WTM + mt * 16 + (lane >> 2);
                int c = ch * 8 + (lane & 3);
                afr[mt][0] = As[r * APITCH + c];
                afr[mt][1] = As[(r + 8) * APITCH + c];
                afr[mt][2] = As[r * APITCH + c + 4];
                afr[mt][3] = As[(r + 8) * APITCH + c + 4];
            }
#pragma unroll
            for (int nt = 0; nt < NT; nt++) {
                int kk = ch * 8 + (lane & 3);
                int n  = wn * WTN + nt * 8 + (lane >> 2);
                bfr[nt][0] = Bs[kk * BPITCH + n];
                bfr[nt][1] = Bs[(kk + 4) * BPITCH + n];
            }
#pragma unroll
            for (int mt = 0; mt < MT; mt++)
#pragma unroll
                for (int nt = 0; nt < NT; nt++)
                    mma_tf32(acc[mt][nt], afr[mt], bfr[nt]);
        }
        __syncthreads();
    }

#pragma unroll
    for (int mt = 0; mt < MT; mt++) {
#pragma unroll
        for (int nt = 0; nt < NT; nt++) {
            int col = n0 + wn * WTN + nt * 8 + (lane & 3) * 2;
            float bx = bias[col], by = bias[col + 1];
            int r0 = m0 + wm * WTM + mt * 16 + (lane >> 2);
            float vx = acc[mt][nt][0] + bx;
            float vy = acc[mt][nt][1] + by;
            if (RELU) { vx = fmaxf(vx, 0.0f); vy = fmaxf(vy, 0.0f); }
            if (r0 < M) {
                *reinterpret_cast<float2*>(&C[(size_t)r0 * Nd + col]) = make_float2(vx, vy);
                if (WH) Ch[((size_t)r0 * Nd + col) >> 1] = __floats2half2_rn(vx, vy);
            }
            int r1 = r0 + 8;
            vx = acc[mt][nt][2] + bx;
            vy = acc[mt][nt][3] + by;
            if (RELU) { vx = fmaxf(vx, 0.0f); vy = fmaxf(vy, 0.0f); }
            if (r1 < M) {
                *reinterpret_cast<float2*>(&C[(size_t)r1 * Nd + col]) = make_float2(vx, vy);
                if (WH) Ch[((size_t)r1 * Nd + col) >> 1] = __floats2half2_rn(vx, vy);
            }
        }
    }
}

// ---------------- Horner SpMV (fp16 gather, fp32 accumulate) ----------------
// acc = a[jadd] * h + gmul * A_hat * vin ;  gmul = (jmul>=0 ? a[jmul] : 1)
__device__ __forceinline__ void spmv_body(const __half2* __restrict__ vin,
                                          const float* __restrict__ h,
                                          int jadd, int jmul, int wid, int lane,
                                          float& accx, float& accy) {
    float aj = g_coef[jadd];
    float gm = (jmul >= 0) ? g_coef[jmul] : 1.0f;
    float2 hv = reinterpret_cast<const float2*>(h)[(size_t)wid * 32 + lane];
    accx = aj * hv.x;
    accy = aj * hv.y;
    int idx = g_start[wid];
    int e   = g_start[wid + 1];
    for (; idx + 8 <= e; idx += 8) {
        int2 ed[8];
        __half2 hvv[8];
#pragma unroll
        for (int q = 0; q < 8; q++) ed[q] = g_edge[idx + q];
#pragma unroll
        for (int q = 0; q < 8; q++) hvv[q] = vin[(size_t)ed[q].x * 32 + lane];
#pragma unroll
        for (int q = 0; q < 8; q++) {
            float w = gm * __int_as_float(ed[q].y);
            float2 f = __half22float2(hvv[q]);
            accx = fmaf(w, f.x, accx);
            accy = fmaf(w, f.y, accy);
        }
    }
    for (; idx < e; ++idx) {
        int2 ed = g_edge[idx];
        float w = gm * __int_as_float(ed.y);
        float2 f = __half22float2(vin[(size_t)ed.x * 32 + lane]);
        accx = fmaf(w, f.x, accx);
        accy = fmaf(w, f.y, accy);
    }
}

__launch_bounds__(256)
__global__ void spmv_h_k(const __half2* __restrict__ vin, __half2* __restrict__ vout,
                         const float* __restrict__ h, int jadd, int jmul) {
    int wid  = (blockIdx.x * blockDim.x + threadIdx.x) >> 5;
    int lane = threadIdx.x & 31;
    if (wid >= N_NODES) return;
    float accx, accy;
    spmv_body(vin, h, jadd, jmul, wid, lane, accx, accy);
    vout[(size_t)wid * 32 + lane] = __floats2half2_rn(accx, accy);
}

// final pass fused with log_softmax over the 64 classes (warp holds full row)
__launch_bounds__(256)
__global__ void spmv_lsm_k(const __half2* __restrict__ vin, float* __restrict__ out,
                           const float* __restrict__ h) {
    int wid  = (blockIdx.x * blockDim.x + threadIdx.x) >> 5;
    int lane = threadIdx.x & 31;
    if (wid >= N_NODES) return;
    float vx, vy;
    spmv_body(vin, h, 0, -1, wid, lane, vx, vy);
    float m = fmaxf(vx, vy);
#pragma unroll
    for (int o = 16; o; o >>= 1) m = fmaxf(m, __shfl_xor_sync(0xFFFFFFFFu, m, o));
    float s = expf(vx - m) + expf(vy - m);
#pragma unroll
    for (int o = 16; o; o >>= 1) s += __shfl_xor_sync(0xFFFFFFFFu, s, o);
    float l = m + logf(s);
    reinterpret_cast<float2*>(out)[(size_t)wid * 32 + lane] = make_float2(vx - l, vy - l);
}

// ---------------- launcher ----------------
extern "C" void kernel_launch(void* const* d_in, const int* in_sizes, int n_in,
                              void* d_out, int out_size) {
    const float* x    = (const float*)d_in[0];
    const int*   ei   = (const int*)  d_in[1];
    const float* W1   = (const float*)d_in[2];
    const float* b1   = (const float*)d_in[3];
    const float* W2   = (const float*)d_in[4];
    const float* b2   = (const float*)d_in[5];
    const float* temp = (const float*)d_in[6];
    float*       out  = (float*)d_out;
    const int* row = ei;
    const int* col = ei + N_EDGES;

    float *ph1, *ph;
    __half2 *phh, *pq0, *pq1;
    cudaGetSymbolAddress((void**)&ph1, g_h1);
    cudaGetSymbolAddress((void**)&ph,  g_h);
    cudaGetSymbolAddress((void**)&phh, g_hh);
    cudaGetSymbolAddress((void**)&pq0, g_q0);
    cudaGetSymbolAddress((void**)&pq1, g_q1);

    // CSR build + coefficients
    zero_cnt_k<<<(N_NODES + 255) / 256, 256>>>();
    hist_k<<<(N_EDGES + 255) / 256, 256>>>(row);
    scan_k<<<1, 1024>>>();
    scatter_k<<<(N_EDGES + 255) / 256, 256>>>(row, col);
    coef_k<<<1, 32>>>(temp);

    // MLP on tensor cores (tf32 mma); GEMM2 also emits fp16 copy of h
    {
        dim3 g1(D_HID / 128, (N_NODES + 127) / 128);
        gemm_tc_k<128, 128, 2, 4, true, false><<<g1, 256>>>(x, W1, b1, ph1, nullptr,
                                                            N_NODES, D_IN, D_HID);
        dim3 g2(D_OUT / 64, (N_NODES + 127) / 128);
        gemm_tc_k<128, 64, 4, 2, false, true><<<g2, 256>>>(ph1, W2, b2, ph, phh,
                                                           N_NODES, D_HID, D_OUT);
    }

    // Horner evaluation: r = aK*h; then r = A r + a_j h, j = K-1 .. 0
    const int warp_blocks = (N_NODES * 32 + 255) / 256;
    // first pass fused with the aK scaling (gather from hh with multiplier aK)
    spmv_h_k<<<warp_blocks, 256>>>(phh, pq0, ph, KORD - 1, KORD);
    __half2* qcur = pq0;
    __half2* qnxt = pq1;
    for (int j = KORD - 2; j >= 1; j--) {
        spmv_h_k<<<warp_blocks, 256>>>(qcur, qnxt, ph, j, -1);
        __half2* t = qcur; qcur = qnxt; qnxt = t;
    }
    // last pass fused with log_softmax
    spmv_lsm_k<<<warp_blocks, 256>>>(qcur, out, ph);
}

// round 10
// speedup vs baseline: 1.5978x; 1.0665x over previous
#include <cuda_runtime.h>
#include <cuda_fp16.h>
#include <math.h>
#include <stdint.h>

#define N_NODES 100000
#define N_EDGES 3200000
#define D_IN    512
#define D_HID   256
#define D_OUT   64
#define KORD    10

#define SCAN_CHUNK   1024
#define NSCAN_BLOCKS ((N_NODES + SCAN_CHUNK - 1) / SCAN_CHUNK)   // 98

// ---------------- device scratch (no allocations allowed) ----------------
__device__ int     g_cnt[N_NODES];
__device__ int     g_pos[N_NODES];
__device__ int     g_start[N_NODES + 1];
__device__ float   g_dinv[N_NODES];
__device__ int     g_bsum[NSCAN_BLOCKS];
__device__ int     g_boff[NSCAN_BLOCKS];
__device__ int2    g_edge[N_EDGES];                        // (col, w bits) CSR by row
__device__ float   g_h1[(size_t)N_NODES * D_HID];          // MLP hidden
__device__ float   g_h [(size_t)N_NODES * D_OUT];          // MLP output fp32
__device__ __half2 g_hh[(size_t)N_NODES * (D_OUT / 2)];    // MLP output fp16
__device__ __half2 g_q0[(size_t)N_NODES * (D_OUT / 2)];    // Horner intermediates (fp16)
__device__ __half2 g_q1[(size_t)N_NODES * (D_OUT / 2)];
__device__ float   g_coef[KORD + 1];                       // monomial coeffs of poly in A

// ---------------- CSR build ----------------
__global__ void zero_cnt_k() {
    int i = blockIdx.x * blockDim.x + threadIdx.x;
    if (i < N_NODES) g_cnt[i] = 0;
}

// 2 edges per thread
__global__ void hist_k(const int* __restrict__ row) {
    int t = blockIdx.x * blockDim.x + threadIdx.x;
    int e0 = t * 2;
    if (e0 >= N_EDGES) return;
    int2 r2 = *reinterpret_cast<const int2*>(&row[e0]);
    atomicAdd(&g_cnt[r2.x], 1);
    atomicAdd(&g_cnt[r2.y], 1);
}

// --- multi-block exclusive scan over g_cnt ---
// A: per-block reduction (256 thr x 4 elems)
__global__ void scanA_k() {
    __shared__ int ws[8];
    int b    = blockIdx.x;
    int tid  = threadIdx.x;
    int lane = tid & 31, warp = tid >> 5;
    int base = b * SCAN_CHUNK + tid * 4;
    int s = 0;
#pragma unroll
    for (int q = 0; q < 4; q++) {
        int i = base + q;
        if (i < N_NODES) s += g_cnt[i];
    }
#pragma unroll
    for (int o = 16; o; o >>= 1) s += __shfl_xor_sync(0xFFFFFFFFu, s, o);
    if (lane == 0) ws[warp] = s;
    __syncthreads();
    if (tid == 0) {
        int t = 0;
#pragma unroll
        for (int q = 0; q < 8; q++) t += ws[q];
        g_bsum[b] = t;
    }
}

// B: single small block scans the 98 block sums (exclusive)
__global__ void scanB_k() {
    __shared__ int ws[4];
    int tid = threadIdx.x, lane = tid & 31, warp = tid >> 5;   // 128 threads
    int v = (tid < NSCAN_BLOCKS) ? g_bsum[tid] : 0;
    int incl = v;
#pragma unroll
    for (int o = 1; o < 32; o <<= 1) {
        int t = __shfl_up_sync(0xFFFFFFFFu, incl, o);
        if (lane >= o) incl += t;
    }
    if (lane == 31) ws[warp] = incl;
    __syncthreads();
    if (warp == 0 && lane < 4) {
        int w = ws[lane];
#pragma unroll
        for (int o = 1; o < 4; o <<= 1) {
            int t = __shfl_up_sync(0xFu, w, o);
            if (lane >= o) w += t;
        }
        ws[lane] = w;
    }
    __syncthreads();
    int woff = (warp > 0) ? ws[warp - 1] : 0;
    if (tid < NSCAN_BLOCKS) g_boff[tid] = woff + incl - v;
    if (tid == 0) g_start[N_NODES] = N_EDGES;
}

// C: per-block rescan + finalize start/pos/dinv
__global__ void scanC_k() {
    __shared__ int ws[8];
    int b    = blockIdx.x;
    int tid  = threadIdx.x;
    int lane = tid & 31, warp = tid >> 5;
    int base = b * SCAN_CHUNK + tid * 4;
    int v[4];
    int ts = 0;
#pragma unroll
    for (int q = 0; q < 4; q++) {
        int i = base + q;
        v[q] = (i < N_NODES) ? g_cnt[i] : 0;
        ts += v[q];
    }
    int incl = ts;
#pragma unroll
    for (int o = 1; o < 32; o <<= 1) {
        int t = __shfl_up_sync(0xFFFFFFFFu, incl, o);
        if (lane >= o) incl += t;
    }
    if (lane == 31) ws[warp] = incl;
    __syncthreads();
    if (warp == 0 && lane < 8) {
        int w = ws[lane];
#pragma unroll
        for (int o = 1; o < 8; o <<= 1) {
            int t = __shfl_up_sync(0xFFu, w, o);
            if (lane >= o) w += t;
        }
        ws[lane] = w;
    }
    __syncthreads();
    int off = g_boff[b] + ((warp > 0) ? ws[warp - 1] : 0) + (incl - ts);
#pragma unroll
    for (int q = 0; q < 4; q++) {
        int i = base + q;
        if (i < N_NODES) {
            g_start[i] = off;
            g_pos[i]   = off;
            g_dinv[i]  = (v[q] > 0) ? rsqrtf((float)v[q]) : 0.0f;
        }
        off += v[q];
    }
}

// 2 edges per thread
__global__ void scatter_k(const int* __restrict__ row, const int* __restrict__ col) {
    int t = blockIdx.x * blockDim.x + threadIdx.x;
    int e0 = t * 2;
    if (e0 >= N_EDGES) return;
    int2 r2 = *reinterpret_cast<const int2*>(&row[e0]);
    int2 c2 = *reinterpret_cast<const int2*>(&col[e0]);
    int p0 = atomicAdd(&g_pos[r2.x], 1);
    g_edge[p0] = make_int2(c2.x, __float_as_int(g_dinv[r2.x] * g_dinv[c2.x]));
    int p1 = atomicAdd(&g_pos[r2.y], 1);
    g_edge[p1] = make_int2(c2.y, __float_as_int(g_dinv[r2.y] * g_dinv[c2.y]));
}

// ---------------- Bernstein -> monomial coefficients (exact in double) ----------------
__global__ void coef_k(const float* __restrict__ temp) {
    if (threadIdx.x != 0 || blockIdx.x != 0) return;
    double B[KORD + 1][KORD + 1];
    for (int n = 0; n <= KORD; n++) {
        for (int j = 0; j <= KORD; j++) B[n][j] = 0.0;
        B[n][0] = 1.0;
        for (int j = 1; j <= n; j++)
            B[n][j] = (j == n) ? 1.0 : (B[n - 1][j - 1] + B[n - 1][j]);
    }
    double a[KORD + 1];
    for (int j = 0; j <= KORD; j++) a[j] = 0.0;
    for (int k = 0; k <= KORD; k++) {
        double th = (double)temp[k];
        if (th < 0.0) th = 0.0;                       // relu
        double ck = th * B[KORD][k] / 1024.0;         // theta_k * C(K,k)/2^K
        for (int j = 0; j <= KORD; j++) {
            double s = 0.0;
            for (int i = 0; i <= k; i++) {
                int l = j - i;
                if (l >= 0 && l <= KORD - k) {
                    double t = B[k][i] * B[KORD - k][l];
                    s += (i & 1) ? -t : t;
                }
            }
            a[j] += ck * s;
        }
    }
    for (int j = 0; j <= KORD; j++) g_coef[j] = (float)a[j];
}

// ---------------- tf32 tensor-core GEMM (mma.sync m16n8k8) ----------------
__device__ __forceinline__ uint32_t f2tf(float f) {
    uint32_t u;
    asm("cvt.rna.tf32.f32 %0, %1;" : "=r"(u) : "f"(f));
    return u;
}

__device__ __forceinline__ void mma_tf32(float* d, const uint32_t* a, const uint32_t* b) {
    asm volatile(
        "mma.sync.aligned.m16n8k8.row.col.f32.tf32.tf32.f32 "
        "{%0,%1,%2,%3}, {%4,%5,%6,%7}, {%8,%9}, {%0,%1,%2,%3};"
        : "+f"(d[0]), "+f"(d[1]), "+f"(d[2]), "+f"(d[3])
        : "r"(a[0]), "r"(a[1]), "r"(a[2]), "r"(a[3]), "r"(b[0]), "r"(b[1]));
}

template <int BM, int BN, int WM, int WN, bool RELU, bool WH>
__launch_bounds__(256)
__global__ void gemm_tc_k(const float* __restrict__ A, const float* __restrict__ B,
                          const float* __restrict__ bias, float* __restrict__ C,
                          __half2* __restrict__ Ch, int M, int Kd, int Nd) {
    constexpr int BK = 16;
    constexpr int APITCH = BK + 4;
    constexpr int BPITCH = BN + 8;
    constexpr int WTM = BM / WM;
    constexpr int WTN = BN / WN;
    constexpr int MT = WTM / 16;
    constexpr int NT = WTN / 8;
    constexpr int AV = (BM * BK) / (256 * 4);
    constexpr int BV = (BK * BN) / (256 * 4);

    __shared__ __align__(16) uint32_t As[BM * APITCH];
    __shared__ __align__(16) uint32_t Bs[BK * BPITCH];

    const int tid  = threadIdx.x;
    const int lane = tid & 31;
    const int w    = tid >> 5;
    const int wm   = w % WM;
    const int wn   = w / WM;
    const int m0   = blockIdx.y * BM;
    const int n0   = blockIdx.x * BN;

    float acc[MT][NT][4];
#pragma unroll
    for (int i = 0; i < MT; i++)
#pragma unroll
        for (int j = 0; j < NT; j++)
#pragma unroll
            for (int q = 0; q < 4; q++) acc[i][j][q] = 0.0f;

    float4 aS[AV], bS[BV];

#pragma unroll
    for (int i = 0; i < AV; i++) {
        int idx = tid + i * 256;
        int r = idx >> 2, cv = (idx & 3) * 4;
        int gm = min(m0 + r, M - 1);
        aS[i] = *reinterpret_cast<const float4*>(&A[(size_t)gm * Kd + cv]);
    }
#pragma unroll
    for (int i = 0; i < BV; i++) {
        int idx = tid + i * 256;
        int r = idx / (BN / 4), c = (idx % (BN / 4)) * 4;
        bS[i] = *reinterpret_cast<const float4*>(&B[(size_t)r * Nd + n0 + c]);
    }

    for (int kt = 0; kt < Kd; kt += BK) {
#pragma unroll
        for (int i = 0; i < AV; i++) {
            int idx = tid + i * 256;
            int r = idx >> 2, cv = (idx & 3) * 4;
            uint4 u = make_uint4(f2tf(aS[i].x), f2tf(aS[i].y), f2tf(aS[i].z), f2tf(aS[i].w));
            *reinterpret_cast<uint4*>(&As[r * APITCH + cv]) = u;
        }
#pragma unroll
        for (int i = 0; i < BV; i++) {
            int idx = tid + i * 256;
            int r = idx / (BN / 4), c = (idx % (BN / 4)) * 4;
            uint4 u = make_uint4(f2tf(bS[i].x), f2tf(bS[i].y), f2tf(bS[i].z), f2tf(bS[i].w));
            *reinterpret_cast<uint4*>(&Bs[r * BPITCH + c]) = u;
        }
        __syncthreads();

        if (kt + BK < Kd) {
#pragma unroll
            for (int i = 0; i < AV; i++) {
                int idx = tid + i * 256;
                int r = idx >> 2, cv = (idx & 3) * 4;
                int gm = min(m0 + r, M - 1);
                aS[i] = *reinterpret_cast<const float4*>(&A[(size_t)gm * Kd + kt + BK + cv]);
            }
#pragma unroll
            for (int i = 0; i < BV; i++) {
                int idx = tid + i * 256;
                int r = idx / (BN / 4), c = (idx % (BN / 4)) * 4;
                bS[i] = *reinterpret_cast<const float4*>(&B[(size_t)(kt + BK + r) * Nd + n0 + c]);
            }
        }

#pragma unroll
        for (int ch = 0; ch < 2; ch++) {
            uint32_t afr[MT][4], bfr[NT][2];
#pragma unroll
            for (int mt = 0; mt < MT; mt++) {
                int r = wm * WTM + mt * 16 + (lane >> 2);
                int c = ch * 8 + (lane & 3);
                afr[mt][0] = As[r * APITCH + c];
                afr[mt][1] = As[(r + 8) * APITCH + c];
                afr[mt][2] = As[r * APITCH + c + 4];
                afr[mt][3] = As[(r + 8) * APITCH + c + 4];
            }
#pragma unroll
            for (int nt = 0; nt < NT; nt++) {
                int kk = ch * 8 + (lane & 3);
                int n  = wn * WTN + nt * 8 + (lane >> 2);
                bfr[nt][0] = Bs[kk * BPITCH + n];
                bfr[nt][1] = Bs[(kk + 4) * BPITCH + n];
            }
#pragma unroll
            for (int mt = 0; mt < MT; mt++)
#pragma unroll
                for (int nt = 0; nt < NT; nt++)
                    mma_tf32(acc[mt][nt], afr[mt], bfr[nt]);
        }
        __syncthreads();
    }

#pragma unroll
    for (int mt = 0; mt < MT; mt++) {
#pragma unroll
        for (int nt = 0; nt < NT; nt++) {
            int col = n0 + wn * WTN + nt * 8 + (lane & 3) * 2;
            float bx = bias[col], by = bias[col + 1];
            int r0 = m0 + wm * WTM + mt * 16 + (lane >> 2);
            float vx = acc[mt][nt][0] + bx;
            float vy = acc[mt][nt][1] + by;
            if (RELU) { vx = fmaxf(vx, 0.0f); vy = fmaxf(vy, 0.0f); }
            if (r0 < M) {
                *reinterpret_cast<float2*>(&C[(size_t)r0 * Nd + col]) = make_float2(vx, vy);
                if (WH) Ch[((size_t)r0 * Nd + col) >> 1] = __floats2half2_rn(vx, vy);
            }
            int r1 = r0 + 8;
            vx = acc[mt][nt][2] + bx;
            vy = acc[mt][nt][3] + by;
            if (RELU) { vx = fmaxf(vx, 0.0f); vy = fmaxf(vy, 0.0f); }
            if (r1 < M) {
                *reinterpret_cast<float2*>(&C[(size_t)r1 * Nd + col]) = make_float2(vx, vy);
                if (WH) Ch[((size_t)r1 * Nd + col) >> 1] = __floats2half2_rn(vx, vy);
            }
        }
    }
}

// ---------------- Horner SpMV (fp16 gather, fp32 accumulate) ----------------
// acc = a[jadd] * h + gmul * A_hat * vin ;  gmul = (jmul>=0 ? a[jmul] : 1)
// 16-edge batches: 16 gather lines in flight per warp.
__device__ __forceinline__ void spmv_body(const __half2* __restrict__ vin,
                                          const float* __restrict__ h,
                                          int jadd, int jmul, int wid, int lane,
                                          float& accx, float& accy) {
    float aj = g_coef[jadd];
    float gm = (jmul >= 0) ? g_coef[jmul] : 1.0f;
    float2 hv = reinterpret_cast<const float2*>(h)[(size_t)wid * 32 + lane];
    accx = aj * hv.x;
    accy = aj * hv.y;
    int idx = g_start[wid];
    int e   = g_start[wid + 1];
    for (; idx + 16 <= e; idx += 16) {
        int2 ed[16];
        __half2 gv[16];
#pragma unroll
        for (int q = 0; q < 16; q++) ed[q] = g_edge[idx + q];
#pragma unroll
        for (int q = 0; q < 16; q++) gv[q] = vin[(size_t)ed[q].x * 32 + lane];
#pragma unroll
        for (int q = 0; q < 16; q++) {
            float w = gm * __int_as_float(ed[q].y);
            float2 f = __half22float2(gv[q]);
            accx = fmaf(w, f.x, accx);
            accy = fmaf(w, f.y, accy);
        }
    }
    for (; idx + 4 <= e; idx += 4) {
        int2 ed[4];
        __half2 gv[4];
#pragma unroll
        for (int q = 0; q < 4; q++) ed[q] = g_edge[idx + q];
#pragma unroll
        for (int q = 0; q < 4; q++) gv[q] = vin[(size_t)ed[q].x * 32 + lane];
#pragma unroll
        for (int q = 0; q < 4; q++) {
            float w = gm * __int_as_float(ed[q].y);
            float2 f = __half22float2(gv[q]);
            accx = fmaf(w, f.x, accx);
            accy = fmaf(w, f.y, accy);
        }
    }
    for (; idx < e; ++idx) {
        int2 ed = g_edge[idx];
        float w = gm * __int_as_float(ed.y);
        float2 f = __half22float2(vin[(size_t)ed.x * 32 + lane]);
        accx = fmaf(w, f.x, accx);
        accy = fmaf(w, f.y, accy);
    }
}

__launch_bounds__(256)
__global__ void spmv_h_k(const __half2* __restrict__ vin, __half2* __restrict__ vout,
                         const float* __restrict__ h, int jadd, int jmul) {
    int wid  = (blockIdx.x * blockDim.x + threadIdx.x) >> 5;
    int lane = threadIdx.x & 31;
    if (wid >= N_NODES) return;
    float accx, accy;
    spmv_body(vin, h, jadd, jmul, wid, lane, accx, accy);
    vout[(size_t)wid * 32 + lane] = __floats2half2_rn(accx, accy);
}

// final pass fused with log_softmax over the 64 classes (warp holds full row)
__launch_bounds__(256)
__global__ void spmv_lsm_k(const __half2* __restrict__ vin, float* __restrict__ out,
                           const float* __restrict__ h) {
    int wid  = (blockIdx.x * blockDim.x + threadIdx.x) >> 5;
    int lane = threadIdx.x & 31;
    if (wid >= N_NODES) return;
    float vx, vy;
    spmv_body(vin, h, 0, -1, wid, lane, vx, vy);
    float m = fmaxf(vx, vy);
#pragma unroll
    for (int o = 16; o; o >>= 1) m = fmaxf(m, __shfl_xor_sync(0xFFFFFFFFu, m, o));
    float s = expf(vx - m) + expf(vy - m);
#pragma unroll
    for (int o = 16; o; o >>= 1) s += __shfl_xor_sync(0xFFFFFFFFu, s, o);
    float l = m + logf(s);
    reinterpret_cast<float2*>(out)[(size_t)wid * 32 + lane] = make_float2(vx - l, vy - l);
}

// ---------------- launcher ----------------
extern "C" void kernel_launch(void* const* d_in, const int* in_sizes, int n_in,
                              void* d_out, int out_size) {
    const float* x    = (const float*)d_in[0];
    const int*   ei   = (const int*)  d_in[1];
    const float* W1   = (const float*)d_in[2];
    const float* b1   = (const float*)d_in[3];
    const float* W2   = (const float*)d_in[4];
    const float* b2   = (const float*)d_in[5];
    const float* temp = (const float*)d_in[6];
    float*       out  = (float*)d_out;
    const int* row = ei;
    const int* col = ei + N_EDGES;

    float *ph1, *ph;
    __half2 *phh, *pq0, *pq1;
    cudaGetSymbolAddress((void**)&ph1, g_h1);
    cudaGetSymbolAddress((void**)&ph,  g_h);
    cudaGetSymbolAddress((void**)&phh, g_hh);
    cudaGetSymbolAddress((void**)&pq0, g_q0);
    cudaGetSymbolAddress((void**)&pq1, g_q1);

    // launches 1-3: zero, hist, coef   (keeps gemm1 as the 4th launch -> ncu target)
    zero_cnt_k<<<(N_NODES + 255) / 256, 256>>>();
    hist_k<<<(N_EDGES / 2 + 255) / 256, 256>>>(row);
    coef_k<<<1, 32>>>(temp);

    // launch 4: GEMM1 (captured by ncu -s 5 -c 1 next round)
    dim3 g1(D_HID / 128, (N_NODES + 127) / 128);
    gemm_tc_k<128, 128, 2, 4, true, false><<<g1, 256>>>(x, W1, b1, ph1, nullptr,
                                                        N_NODES, D_IN, D_HID);

    // CSR: multi-block scan + scatter
    scanA_k<<<NSCAN_BLOCKS, 256>>>();
    scanB_k<<<1, 128>>>();
    scanC_k<<<NSCAN_BLOCKS, 256>>>();
    scatter_k<<<(N_EDGES / 2 + 255) / 256, 256>>>(row, col);

    // GEMM2 (also emits fp16 copy of h)
    dim3 g2(D_OUT / 64, (N_NODES + 127) / 128);
    gemm_tc_k<128, 64, 4, 2, false, true><<<g2, 256>>>(ph1, W2, b2, ph, phh,
                                                       N_NODES, D_HID, D_OUT);

    // Horner evaluation: r = aK*h; then r = A r + a_j h, j = K-1 .. 0
    const int warp_blocks = (N_NODES * 32 + 255) / 256;
    spmv_h_k<<<warp_blocks, 256>>>(phh, pq0, ph, KORD - 1, KORD);
    __half2* qcur = pq0;
    __half2* qnxt = pq1;
    for (int j = KORD - 2; j >= 1; j--) {
        spmv_h_k<<<warp_blocks, 256>>>(qcur, qnxt, ph, j, -1);
        __half2* t = qcur; qcur = qnxt; qnxt = t;
    }
    // last pass fused with log_softmax
    spmv_lsm_k<<<warp_blocks, 256>>>(qcur, out, ph);
}

// round 12
// speedup vs baseline: 1.8332x; 1.1474x over previous
#include <cuda_runtime.h>
#include <cuda_fp16.h>
#include <math.h>
#include <stdint.h>

#define N_NODES 100000
#define N_EDGES 3200000
#define D_IN    512
#define D_HID   256
#define D_OUT   64
#define KORD    10

#define SCAN_CHUNK   1024
#define NSCAN_BLOCKS ((N_NODES + SCAN_CHUNK - 1) / SCAN_CHUNK)   // 98

// ---------------- device scratch (no allocations allowed) ----------------
__device__ int     g_cnt[N_NODES];
__device__ int     g_pos[N_NODES];
__device__ int     g_start[N_NODES + 1];
__device__ float   g_dinv[N_NODES];
__device__ int     g_bsum[NSCAN_BLOCKS];
__device__ int     g_boff[NSCAN_BLOCKS];
__device__ int2    g_edge[N_EDGES];                        // (col, w bits) CSR by row
__device__ __half  g_w1h[(size_t)D_HID * D_IN];            // W1^T fp16 [256][512]
__device__ __half  g_w2h[(size_t)D_OUT * D_HID];           // W2^T fp16 [64][256]
__device__ __half  g_h1h[(size_t)N_NODES * D_HID];         // MLP hidden fp16
__device__ float   g_h [(size_t)N_NODES * D_OUT];          // MLP output fp32
__device__ __half2 g_hh[(size_t)N_NODES * (D_OUT / 2)];    // MLP output fp16
__device__ __half2 g_q0[(size_t)N_NODES * (D_OUT / 2)];    // Horner intermediates (fp16)
__device__ __half2 g_q1[(size_t)N_NODES * (D_OUT / 2)];
__device__ float   g_coef[KORD + 1];                       // monomial coeffs of poly in A

// ---------------- CSR build ----------------
__global__ void zero_cnt_k() {
    int i = blockIdx.x * blockDim.x + threadIdx.x;
    if (i < N_NODES) g_cnt[i] = 0;
}

// 2 edges per thread
__global__ void hist_k(const int* __restrict__ row) {
    int t = blockIdx.x * blockDim.x + threadIdx.x;
    int e0 = t * 2;
    if (e0 >= N_EDGES) return;
    int2 r2 = *reinterpret_cast<const int2*>(&row[e0]);
    atomicAdd(&g_cnt[r2.x], 1);
    atomicAdd(&g_cnt[r2.y], 1);
}

// --- multi-block exclusive scan over g_cnt ---
__global__ void scanA_k() {
    __shared__ int ws[8];
    int b    = blockIdx.x;
    int tid  = threadIdx.x;
    int lane = tid & 31, warp = tid >> 5;
    int base = b * SCAN_CHUNK + tid * 4;
    int s = 0;
#pragma unroll
    for (int q = 0; q < 4; q++) {
        int i = base + q;
        if (i < N_NODES) s += g_cnt[i];
    }
#pragma unroll
    for (int o = 16; o; o >>= 1) s += __shfl_xor_sync(0xFFFFFFFFu, s, o);
    if (lane == 0) ws[warp] = s;
    __syncthreads();
    if (tid == 0) {
        int t = 0;
#pragma unroll
        for (int q = 0; q < 8; q++) t += ws[q];
        g_bsum[b] = t;
    }
}

__global__ void scanB_k() {
    __shared__ int ws[4];
    int tid = threadIdx.x, lane = tid & 31, warp = tid >> 5;   // 128 threads
    int v = (tid < NSCAN_BLOCKS) ? g_bsum[tid] : 0;
    int incl = v;
#pragma unroll
    for (int o = 1; o < 32; o <<= 1) {
        int t = __shfl_up_sync(0xFFFFFFFFu, incl, o);
        if (lane >= o) incl += t;
    }
    if (lane == 31) ws[warp] = incl;
    __syncthreads();
    if (warp == 0 && lane < 4) {
        int w = ws[lane];
#pragma unroll
        for (int o = 1; o < 4; o <<= 1) {
            int t = __shfl_up_sync(0xFu, w, o);
            if (lane >= o) w += t;
        }
        ws[lane] = w;
    }
    __syncthreads();
    int woff = (warp > 0) ? ws[warp - 1] : 0;
    if (tid < NSCAN_BLOCKS) g_boff[tid] = woff + incl - v;
    if (tid == 0) g_start[N_NODES] = N_EDGES;
}

__global__ void scanC_k() {
    __shared__ int ws[8];
    int b    = blockIdx.x;
    int tid  = threadIdx.x;
    int lane = tid & 31, warp = tid >> 5;
    int base = b * SCAN_CHUNK + tid * 4;
    int v[4];
    int ts = 0;
#pragma unroll
    for (int q = 0; q < 4; q++) {
        int i = base + q;
        v[q] = (i < N_NODES) ? g_cnt[i] : 0;
        ts += v[q];
    }
    int incl = ts;
#pragma unroll
    for (int o = 1; o < 32; o <<= 1) {
        int t = __shfl_up_sync(0xFFFFFFFFu, incl, o);
        if (lane >= o) incl += t;
    }
    if (lane == 31) ws[warp] = incl;
    __syncthreads();
    if (warp == 0 && lane < 8) {
        int w = ws[lane];
#pragma unroll
        for (int o = 1; o < 8; o <<= 1) {
            int t = __shfl_up_sync(0xFFu, w, o);
            if (lane >= o) w += t;
        }
        ws[lane] = w;
    }
    __syncthreads();
    int off = g_boff[b] + ((warp > 0) ? ws[warp - 1] : 0) + (incl - ts);
#pragma unroll
    for (int q = 0; q < 4; q++) {
        int i = base + q;
        if (i < N_NODES) {
            g_start[i] = off;
            g_pos[i]   = off;
            g_dinv[i]  = (v[q] > 0) ? rsqrtf((float)v[q]) : 0.0f;
        }
        off += v[q];
    }
}

// 2 edges per thread
__global__ void scatter_k(const int* __restrict__ row, const int* __restrict__ col) {
    int t = blockIdx.x * blockDim.x + threadIdx.x;
    int e0 = t * 2;
    if (e0 >= N_EDGES) return;
    int2 r2 = *reinterpret_cast<const int2*>(&row[e0]);
    int2 c2 = *reinterpret_cast<const int2*>(&col[e0]);
    int p0 = atomicAdd(&g_pos[r2.x], 1);
    g_edge[p0] = make_int2(c2.x, __float_as_int(g_dinv[r2.x] * g_dinv[c2.x]));
    int p1 = atomicAdd(&g_pos[r2.y], 1);
    g_edge[p1] = make_int2(c2.y, __float_as_int(g_dinv[r2.y] * g_dinv[c2.y]));
}

// ---------------- W1/W2 -> fp16 transposed ----------------
__global__ void convW_k(const float* __restrict__ W1, const float* __restrict__ W2) {
    int i = blockIdx.x * blockDim.x + threadIdx.x;
    if (i < D_IN * D_HID) {
        int k = i / D_HID, n = i % D_HID;          // W1[k][n]
        g_w1h[(size_t)n * D_IN + k] = __float2half_rn(W1[i]);
    }
    int j = i - D_IN * D_HID;
    if (j >= 0 && j < D_HID * D_OUT) {
        int k = j / D_OUT, n = j % D_OUT;          // W2[k][n]
        g_w2h[(size_t)n * D_HID + k] = __float2half_rn(W2[j]);
    }
}

// ---------------- Bernstein -> monomial coefficients (exact in double) ----------------
__global__ void coef_k(const float* __restrict__ temp) {
    if (threadIdx.x != 0 || blockIdx.x != 0) return;
    double B[KORD + 1][KORD + 1];
    for (int n = 0; n <= KORD; n++) {
        for (int j = 0; j <= KORD; j++) B[n][j] = 0.0;
        B[n][0] = 1.0;
        for (int j = 1; j <= n; j++)
            B[n][j] = (j == n) ? 1.0 : (B[n - 1][j - 1] + B[n - 1][j]);
    }
    double a[KORD + 1];
    for (int j = 0; j <= KORD; j++) a[j] = 0.0;
    for (int k = 0; k <= KORD; k++) {
        double th = (double)temp[k];
        if (th < 0.0) th = 0.0;                       // relu
        double ck = th * B[KORD][k] / 1024.0;         // theta_k * C(K,k)/2^K
        for (int j = 0; j <= KORD; j++) {
            double s = 0.0;
            for (int i = 0; i <= k; i++) {
                int l = j - i;
                if (l >= 0 && l <= KORD - k) {
                    double t = B[k][i] * B[KORD - k][l];
                    s += (i & 1) ? -t : t;
                }
            }
            a[j] += ck * s;
        }
    }
    for (int j = 0; j <= KORD; j++) g_coef[j] = (float)a[j];
}

// ---------------- fp16 tensor-core GEMM (mma.sync m16n8k16) ----------------
__device__ __forceinline__ void mma_f16(float* d, const uint32_t* a, const uint32_t* b) {
    asm volatile(
        "mma.sync.aligned.m16n8k16.row.col.f32.f16.f16.f32 "
        "{%0,%1,%2,%3}, {%4,%5,%6,%7}, {%8,%9}, {%0,%1,%2,%3};"
        : "+f"(d[0]), "+f"(d[1]), "+f"(d[2]), "+f"(d[3])
        : "r"(a[0]), "r"(a[1]), "r"(a[2]), "r"(a[3]), "r"(b[0]), "r"(b[1]));
}

// A: [M,Kd] row-major (fp32 if AF32, converted inline; else fp16).
// Bt: [Nd,Kd] fp16 (pre-transposed). C = relu?(A@B + bias).
// WF: write fp32 C ; WH: write fp16 copy to Ch.
template <int BM, int BN, int WM, int WN, bool AF32, bool RELU, bool WF, bool WH>
__launch_bounds__(256)
__global__ void gemm_h_k(const void* __restrict__ Ain, const __half* __restrict__ Bt,
                         const float* __restrict__ bias, float* __restrict__ C,
                         __half2* __restrict__ Ch, int M, int Kd, int Nd) {
    constexpr int BK = 32;
    constexpr int APITCH = BK + 8;                 // halves
    constexpr int BPITCH = BK + 8;
    constexpr int WTM = BM / WM;
    constexpr int WTN = BN / WN;
    constexpr int MT = WTM / 16;
    constexpr int NT = WTN / 8;
    constexpr int AV4 = (BM * BK) / (256 * 4);     // fp32 A: float4 loads / thread
    constexpr int AVH = (BM * BK) / (256 * 8);     // fp16 A: uint4 loads / thread
    constexpr int BV  = (BN * BK) / (256 * 8);     // fp16 B: uint4 loads / thread

    __shared__ __align__(16) __half As[BM * APITCH];
    __shared__ __align__(16) __half Bs[BN * BPITCH];

    const float*  Af = (const float*)Ain;
    const __half* Ah = (const __half*)Ain;

    const int tid  = threadIdx.x;
    const int lane = tid & 31;
    const int w    = tid >> 5;
    const int wm   = w % WM;
    const int wn   = w / WM;
    const int m0   = blockIdx.y * BM;
    const int n0   = blockIdx.x * BN;

    float acc[MT][NT][4];
#pragma unroll
    for (int i = 0; i < MT; i++)
#pragma unroll
        for (int j = 0; j < NT; j++)
#pragma unroll
            for (int q = 0; q < 4; q++) acc[i][j][q] = 0.0f;

    float4 aSf[AF32 ? AV4 : 1];
    uint4  aSh[AF32 ? 1 : AVH];
    uint4  bS[BV];

    // prefetch tile 0
    if (AF32) {
#pragma unroll
        for (int i = 0; i < AV4; i++) {
            int idx = tid + i * 256;
            int r = idx >> 3, c = (idx & 7) * 4;
            int gm = min(m0 + r, M - 1);
            aSf[i] = *reinterpret_cast<const float4*>(&Af[(size_t)gm * Kd + c]);
        }
    } else {
#pragma unroll
        for (int i = 0; i < AVH; i++) {
            int idx = tid + i * 256;
            int r = idx >> 2, c = (idx & 3) * 8;
            int gm = min(m0 + r, M - 1);
            aSh[i] = *reinterpret_cast<const uint4*>(&Ah[(size_t)gm * Kd + c]);
        }
    }
#pragma unroll
    for (int i = 0; i < BV; i++) {
        int idx = tid + i * 256;
        int n = idx >> 2, kg = (idx & 3) * 8;
        bS[i] = *reinterpret_cast<const uint4*>(&Bt[(size_t)(n0 + n) * Kd + kg]);
    }

    for (int kt = 0; kt < Kd; kt += BK) {
        // stage regs -> smem
        if (AF32) {
#pragma unroll
            for (int i = 0; i < AV4; i++) {
                int idx = tid + i * 256;
                int r = idx >> 3, c = (idx & 7) * 4;
                __half2 lo = __floats2half2_rn(aSf[i].x, aSf[i].y);
                __half2 hi = __floats2half2_rn(aSf[i].z, aSf[i].w);
                *reinterpret_cast<uint2*>(&As[r * APITCH + c]) =
                    make_uint2(*(uint32_t*)&lo, *(uint32_t*)&hi);
            }
        } else {
#pragma unroll
            for (int i = 0; i < AVH; i++) {
                int idx = tid + i * 256;
                int r = idx >> 2, c = (idx & 3) * 8;
                *reinterpret_cast<uint4*>(&As[r * APITCH + c]) = aSh[i];
            }
        }
#pragma unroll
        for (int i = 0; i < BV; i++) {
            int idx = tid + i * 256;
            int n = idx >> 2, kg = (idx & 3) * 8;
            *reinterpret_cast<uint4*>(&Bs[n * BPITCH + kg]) = bS[i];
        }
        __syncthreads();

        // prefetch next tile
        if (kt + BK < Kd) {
            if (AF32) {
#pragma unroll
                for (int i = 0; i < AV4; i++) {
                    int idx = tid + i * 256;
                    int r = idx >> 3, c = (idx & 7) * 4;
                    int gm = min(m0 + r, M - 1);
                    aSf[i] = *reinterpret_cast<const float4*>(&Af[(size_t)gm * Kd + kt + BK + c]);
                }
            } else {
#pragma unroll
                for (int i = 0; i < AVH; i++) {
                    int idx = tid + i * 256;
                    int r = idx >> 2, c = (idx & 3) * 8;
                    int gm = min(m0 + r, M - 1);
                    aSh[i] = *reinterpret_cast<const uint4*>(&Ah[(size_t)gm * Kd + kt + BK + c]);
                }
            }
#pragma unroll
            for (int i = 0; i < BV; i++) {
                int idx = tid + i * 256;
                int n = idx >> 2, kg = (idx & 3) * 8;
                bS[i] = *reinterpret_cast<const uint4*>(&Bt[(size_t)(n0 + n) * Kd + kt + BK + kg]);
            }
        }

        // compute: 2 chunks of k16
#pragma unroll
        for (int ch = 0; ch < 2; ch++) {
            const int c0 = ch * 16 + (lane & 3) * 2;
            uint32_t afr[MT][4], bfr[NT][2];
#pragma unroll
            for (int mt = 0; mt < MT; mt++) {
                int r = wm * WTM + mt * 16 + (lane >> 2);
                afr[mt][0] = *reinterpret_cast<const uint32_t*>(&As[r * APITCH + c0]);
                afr[mt][1] = *reinterpret_cast<const uint32_t*>(&As[(r + 8) * APITCH + c0]);
                afr[mt][2] = *reinterpret_cast<const uint32_t*>(&As[r * APITCH + c0 + 8]);
                afr[mt][3] = *reinterpret_cast<const uint32_t*>(&As[(r + 8) * APITCH + c0 + 8]);
            }
#pragma unroll
            for (int nt = 0; nt < NT; nt++) {
                int n = wn * WTN + nt * 8 + (lane >> 2);
                bfr[nt][0] = *reinterpret_cast<const uint32_t*>(&Bs[n * BPITCH + c0]);
                bfr[nt][1] = *reinterpret_cast<const uint32_t*>(&Bs[n * BPITCH + c0 + 8]);
            }
#pragma unroll
            for (int mt = 0; mt < MT; mt++)
#pragma unroll
                for (int nt = 0; nt < NT; nt++)
                    mma_f16(acc[mt][nt], afr[mt], bfr[nt]);
        }
        __syncthreads();
    }

    // epilogue: bias (+relu)
#pragma unroll
    for (int mt = 0; mt < MT; mt++) {
#pragma unroll
        for (int nt = 0; nt < NT; nt++) {
            int col = n0 + wn * WTN + nt * 8 + (lane & 3) * 2;
            float bx = bias[col], by = bias[col + 1];
            int r0 = m0 + wm * WTM + mt * 16 + (lane >> 2);
            float vx = acc[mt][nt][0] + bx;
            float vy = acc[mt][nt][1] + by;
            if (RELU) { vx = fmaxf(vx, 0.0f); vy = fmaxf(vy, 0.0f); }
            if (r0 < M) {
                if (WF) *reinterpret_cast<float2*>(&C[(size_t)r0 * Nd + col]) = make_float2(vx, vy);
                if (WH) Ch[((size_t)r0 * Nd + col) >> 1] = __floats2half2_rn(vx, vy);
            }
            int r1 = r0 + 8;
            vx = acc[mt][nt][2] + bx;
            vy = acc[mt][nt][3] + by;
            if (RELU) { vx = fmaxf(vx, 0.0f); vy = fmaxf(vy, 0.0f); }
            if (r1 < M) {
                if (WF) *reinterpret_cast<float2*>(&C[(size_t)r1 * Nd + col]) = make_float2(vx, vy);
                if (WH) Ch[((size_t)r1 * Nd + col) >> 1] = __floats2half2_rn(vx, vy);
            }
        }
    }
}

// ---------------- Horner SpMV (fp16 gather, fp32 accumulate) ----------------
__device__ __forceinline__ void spmv_body(const __half2* __restrict__ vin,
                                          const float* __restrict__ h,
                                          int jadd, int jmul, int wid, int lane,
                                          float& accx, float& accy) {
    float aj = g_coef[jadd];
    float gm = (jmul >= 0) ? g_coef[jmul] : 1.0f;
    float2 hv = reinterpret_cast<const float2*>(h)[(size_t)wid * 32 + lane];
    accx = aj * hv.x;
    accy = aj * hv.y;
    int idx = g_start[wid];
    int e   = g_start[wid + 1];
    for (; idx + 16 <= e; idx += 16) {
        int2 ed[16];
        __half2 gv[16];
#pragma unroll
        for (int q = 0; q < 16; q++) ed[q] = g_edge[idx + q];
#pragma unroll
        for (int q = 0; q < 16; q++) gv[q] = vin[(size_t)ed[q].x * 32 + lane];
#pragma unroll
        for (int q = 0; q < 16; q++) {
            float w = gm * __int_as_float(ed[q].y);
            float2 f = __half22float2(gv[q]);
            accx = fmaf(w, f.x, accx);
            accy = fmaf(w, f.y, accy);
        }
    }
    for (; idx + 4 <= e; idx += 4) {
        int2 ed[4];
        __half2 gv[4];
#pragma unroll
        for (int q = 0; q < 4; q++) ed[q] = g_edge[idx + q];
#pragma unroll
        for (int q = 0; q < 4; q++) gv[q] = vin[(size_t)ed[q].x * 32 + lane];
#pragma unroll
        for (int q = 0; q < 4; q++) {
            float w = gm * __int_as_float(ed[q].y);
            float2 f = __half22float2(gv[q]);
            accx = fmaf(w, f.x, accx);
            accy = fmaf(w, f.y, accy);
        }
    }
    for (; idx < e; ++idx) {
        int2 ed = g_edge[idx];
        float w = gm * __int_as_float(ed.y);
        float2 f = __half22float2(vin[(size_t)ed.x * 32 + lane]);
        accx = fmaf(w, f.x, accx);
        accy = fmaf(w, f.y, accy);
    }
}

__launch_bounds__(256)
__global__ void spmv_h_k(const __half2* __restrict__ vin, __half2* __restrict__ vout,
                         const float* __restrict__ h, int jadd, int jmul) {
    int wid  = (blockIdx.x * blockDim.x + threadIdx.x) >> 5;
    int lane = threadIdx.x & 31;
    if (wid >= N_NODES) return;
    float accx, accy;
    spmv_body(vin, h, jadd, jmul, wid, lane, accx, accy);
    vout[(size_t)wid * 32 + lane] = __floats2half2_rn(accx, accy);
}

// final pass fused with log_softmax over the 64 classes (warp holds full row)
__launch_bounds__(256)
__global__ void spmv_lsm_k(const __half2* __restrict__ vin, float* __restrict__ out,
                           const float* __restrict__ h) {
    int wid  = (blockIdx.x * blockDim.x + threadIdx.x) >> 5;
    int lane = threadIdx.x & 31;
    if (wid >= N_NODES) return;
    float vx, vy;
    spmv_body(vin, h, 0, -1, wid, lane, vx, vy);
    float m = fmaxf(vx, vy);
#pragma unroll
    for (int o = 16; o; o >>= 1) m = fmaxf(m, __shfl_xor_sync(0xFFFFFFFFu, m, o));
    float s = expf(vx - m) + expf(vy - m);
#pragma unroll
    for (int o = 16; o; o >>= 1) s += __shfl_xor_sync(0xFFFFFFFFu, s, o);
    float l = m + logf(s);
    reinterpret_cast<float2*>(out)[(size_t)wid * 32 + lane] = make_float2(vx - l, vy - l);
}

// ---------------- launcher ----------------
extern "C" void kernel_launch(void* const* d_in, const int* in_sizes, int n_in,
                              void* d_out, int out_size) {
    const float* x    = (const float*)d_in[0];
    const int*   ei   = (const int*)  d_in[1];
    const float* W1   = (const float*)d_in[2];
    const float* b1   = (const float*)d_in[3];
    const float* W2   = (const float*)d_in[4];
    const float* b2   = (const float*)d_in[5];
    const float* temp = (const float*)d_in[6];
    float*       out  = (float*)d_out;
    const int* row = ei;
    const int* col = ei + N_EDGES;

    float *ph;
    __half *pw1h, *pw2h, *ph1h;
    __half2 *phh, *pq0, *pq1;
    cudaGetSymbolAddress((void**)&pw1h, g_w1h);
    cudaGetSymbolAddress((void**)&pw2h, g_w2h);
    cudaGetSymbolAddress((void**)&ph1h, g_h1h);
    cudaGetSymbolAddress((void**)&ph,   g_h);
    cudaGetSymbolAddress((void**)&phh,  g_hh);
    cudaGetSymbolAddress((void**)&pq0,  g_q0);
    cudaGetSymbolAddress((void**)&pq1,  g_q1);

    // launches 1-3 (keeps GEMM1 as the 4th launch -> ncu target next round)
    zero_cnt_k<<<(N_NODES + 255) / 256, 256>>>();
    hist_k<<<(N_EDGES / 2 + 255) / 256, 256>>>(row);
    convW_k<<<(D_IN * D_HID + D_HID * D_OUT + 255) / 256, 256>>>(W1, W2);

    // launch 4: GEMM1 (fp16 MMA, inline fp32->fp16 A conversion), h1 out fp16
    {
        dim3 g1(D_HID / 128, (N_NODES + 127) / 128);
        gemm_h_k<128, 128, 2, 4, true, true, false, true>
            <<<g1, 256>>>(x, pw1h, b1, nullptr, (__half2*)ph1h, N_NODES, D_IN, D_HID);
    }

    coef_k<<<1, 32>>>(temp);

    // CSR: multi-block scan + scatter
    scanA_k<<<NSCAN_BLOCKS, 256>>>();
    scanB_k<<<1, 128>>>();
    scanC_k<<<NSCAN_BLOCKS, 256>>>();
    scatter_k<<<(N_EDGES / 2 + 255) / 256, 256>>>(row, col);

    // GEMM2 (all fp16 in, fp32 + fp16 out)
    {
        dim3 g2(D_OUT / 64, (N_NODES + 127) / 128);
        gemm_h_k<128, 64, 4, 2, false, false, true, true>
            <<<g2, 256>>>(ph1h, pw2h, b2, ph, phh, N_NODES, D_HID, D_OUT);
    }

    // Horner evaluation: r = aK*h; then r = A r + a_j h, j = K-1 .. 0
    const int warp_blocks = (N_NODES * 32 + 255) / 256;
    spmv_h_k<<<warp_blocks, 256>>>(phh, pq0, ph, KORD - 1, KORD);
    __half2* qcur = pq0;
    __half2* qnxt = pq1;
    for (int j = KORD - 2; j >= 1; j--) {
        spmv_h_k<<<warp_blocks, 256>>>(qcur, qnxt, ph, j, -1);
        __half2* t = qcur; qcur = qnxt; qnxt = t;
    }
    // last pass fused with log_softmax
    spmv_lsm_k<<<warp_blocks, 256>>>(qcur, out, ph);
}